// round 16
// baseline (speedup 1.0000x reference)
#include <cuda_runtime.h>
#include <math.h>
#include <float.h>
#include <stdint.h>

// ---------------- problem constants ----------------
#define TT   2048
#define HD   2048
#define NHQ  16
#define NHKV 4
#define DH   128
#define NE   16
#define NI   768

// ---------------- device scratch ----------------
__device__ float g_q[TT * NHQ * DH];
__device__ float g_k[TT * NHKV * DH];
__device__ float g_v[TT * NHKV * DH];
__device__ float g_attn[TT * NHQ * DH];
__device__ float g_h[TT * HD];
__device__ int   g_sel[TT * 2];
__device__ int   g_cnt[NE];
__device__ int   g_off[NE];
__device__ int   g_fill[NE];
__device__ int   g_tok[TT * 2];
__device__ int   g_slot[TT * 2];
__device__ float g_up[TT * 2 * NI];
__device__ float g_down[TT * 2 * HD];
// flat m-tile table + completion counters
__device__ int   g_mt_e[64];
__device__ int   g_mt_bm[64];
__device__ int   g_nmt;
__device__ int   g_upc[64];
__device__ int   g_dnc;
__device__ int   g_hc[16];
__device__ int   g_rc;

// ---------------- helpers ----------------
__device__ __forceinline__ float fexp2(float x) {
    float y;
    asm("ex2.approx.ftz.f32 %0, %1;" : "=f"(y) : "f"(x));
    return y;
}

__device__ __forceinline__ void mma_tf32(float c[4], const uint32_t a[4], const uint32_t b[2]) {
    asm volatile(
        "mma.sync.aligned.m16n8k8.row.col.f32.tf32.tf32.f32 "
        "{%0,%1,%2,%3}, {%4,%5,%6,%7}, {%8,%9}, {%0,%1,%2,%3};"
        : "+f"(c[0]), "+f"(c[1]), "+f"(c[2]), "+f"(c[3])
        : "r"(a[0]), "r"(a[1]), "r"(a[2]), "r"(a[3]), "r"(b[0]), "r"(b[1]));
}

__device__ __forceinline__ void ldsm4(uint32_t a[4], uint32_t addr) {
    asm volatile("ldmatrix.sync.aligned.m8n8.x4.shared.b16 {%0,%1,%2,%3}, [%4];"
                 : "=r"(a[0]), "=r"(a[1]), "=r"(a[2]), "=r"(a[3]) : "r"(addr));
}

__device__ __forceinline__ void cpa16(uint32_t dst, const void* src, bool pred) {
    int sz = pred ? 16 : 0;
    asm volatile("cp.async.cg.shared.global [%0], [%1], 16, %2;\n"
                 :: "r"(dst), "l"(src), "r"(sz));
}
__device__ __forceinline__ void cp_commit() {
    asm volatile("cp.async.commit_group;\n" ::: "memory");
}
__device__ __forceinline__ void cp_wait0() {
    asm volatile("cp.async.wait_group 0;\n" ::: "memory");
}
__device__ __forceinline__ void cp_wait1() {
    asm volatile("cp.async.wait_group 1;\n" ::: "memory");
}

// ---------------- mma.sync tf32 GEMM core ----------------
#define AST 36
#define BST 136
#define ASZ (128 * AST)
#define BSZ (32 * BST)
#define NSTG 3
#define GEMM_SMEM ((NSTG * ASZ + NSTG * BSZ) * 4)

template<bool GATHER, bool BIAS, bool SILU, bool RESID, bool QKROPE>
__device__ __forceinline__ void gemm_tc(
    const float* __restrict__ A, int lda, const int* __restrict__ gidx,
    const float* __restrict__ B, int ldb,
    float* __restrict__ C, int ldc,
    const float* __restrict__ bias,
    const float* __restrict__ resid,
    int M, int K, int bm, int bn,
    const float* __restrict__ nsc = nullptr, int tok0 = 0)
{
    extern __shared__ float smem[];
    float* As = smem;
    float* Bs = smem + NSTG * ASZ;

    const int tid  = threadIdx.x;
    const int wid  = tid >> 5;
    const int lane = tid & 31;
    const int warp_m = (wid >> 2) * 64;
    const int warp_n = (wid & 3) * 32;
    const int lr = lane >> 2;
    const int lc = lane & 3;
    const int lrow = lane & 7;
    const int sel  = lane >> 3;

    float c[4][4][4];
#pragma unroll
    for (int mt = 0; mt < 4; mt++)
#pragma unroll
        for (int nt = 0; nt < 4; nt++)
#pragma unroll
            for (int i = 0; i < 4; i++) c[mt][nt][i] = 0.f;

    const int am  = tid >> 3;
    const int ak4 = (tid & 7) * 4;
    const int bk  = tid >> 5;
    const int bn4 = (tid & 31) * 4;

    const float* asrc[4];
    bool aok[4];
#pragma unroll
    for (int i = 0; i < 4; i++) {
        int grow = bm + am + 32 * i;
        aok[i] = (grow < M);
        const float* p = A;
        if (aok[i]) p = A + (size_t)(GATHER ? gidx[grow] : grow) * lda;
        asrc[i] = p + ak4;
    }
    const float* bsrc[4];
#pragma unroll
    for (int i = 0; i < 4; i++)
        bsrc[i] = B + (size_t)(bk + 8 * i) * ldb + bn + bn4;

    uint32_t sa = (uint32_t)__cvta_generic_to_shared(As);
    uint32_t sb = (uint32_t)__cvta_generic_to_shared(Bs);
    uint32_t adst[4], bdst[4];
#pragma unroll
    for (int i = 0; i < 4; i++) {
        adst[i] = sa + ((am + 32 * i) * AST + ak4) * 4;
        bdst[i] = sb + ((bk + 8 * i) * BST + bn4) * 4;
    }

    const uint32_t a_lane4 = (((sel & 1) * 8 + lrow) * AST + (sel >> 1) * 4) * 4;
    const uint32_t a_warp = sa + warp_m * AST * 4 + a_lane4;

    const int nch = K >> 5;

#pragma unroll
    for (int i = 0; i < 4; i++) cpa16(adst[i], asrc[i], aok[i]);
#pragma unroll
    for (int i = 0; i < 4; i++) cpa16(bdst[i], bsrc[i], true);
    cp_commit();
    if (nch > 1) {
#pragma unroll
        for (int i = 0; i < 4; i++) cpa16(adst[i] + ASZ * 4, asrc[i] + 32, aok[i]);
#pragma unroll
        for (int i = 0; i < 4; i++) cpa16(bdst[i] + BSZ * 4, bsrc[i] + (size_t)32 * ldb, true);
        cp_commit();
    }

    int sc = 0;
    int sn = (nch > 1) ? 2 : 1;
    for (int ch = 0; ch < nch; ch++) {
        if (ch + 1 < nch) cp_wait1(); else cp_wait0();
        __syncthreads();

        if (ch + 2 < nch) {
            const int koff = (ch + 2) * 32;
            const uint32_t ao = sn * (ASZ * 4);
            const uint32_t bo = sn * (BSZ * 4);
#pragma unroll
            for (int i = 0; i < 4; i++) cpa16(adst[i] + ao, asrc[i] + koff, aok[i]);
#pragma unroll
            for (int i = 0; i < 4; i++) cpa16(bdst[i] + bo, bsrc[i] + (size_t)koff * ldb, true);
            cp_commit();
            sn = (sn + 1 == NSTG) ? 0 : sn + 1;
        }

        const float* Bc = Bs + sc * BSZ;
        const uint32_t a_base = a_warp + sc * (ASZ * 4);
        sc = (sc + 1 == NSTG) ? 0 : sc + 1;

#pragma unroll
        for (int ks = 0; ks < 4; ks++) {
            const int kb = ks * 8;
            uint32_t a[4][4];
#pragma unroll
            for (int mt = 0; mt < 4; mt++)
                ldsm4(a[mt], a_base + mt * (16 * AST * 4) + ks * 32);

            uint32_t b[4][2];
#pragma unroll
            for (int nt = 0; nt < 4; nt++) {
                int col = warp_n + nt * 8 + lr;
                b[nt][0] = __float_as_uint(Bc[(kb + lc) * BST + col]);
                b[nt][1] = __float_as_uint(Bc[(kb + 4 + lc) * BST + col]);
            }
#pragma unroll
            for (int mt = 0; mt < 4; mt++)
#pragma unroll
                for (int nt = 0; nt < 4; nt++)
                    mma_tf32(c[mt][nt], a[mt], b[nt]);
        }
    }

    if (QKROPE) {
        __syncthreads();
        float* st = smem;
#pragma unroll
        for (int mt = 0; mt < 4; mt++)
#pragma unroll
            for (int hh = 0; hh < 2; hh++) {
                int row = warp_m + mt * 16 + hh * 8 + lr;
#pragma unroll
                for (int nt = 0; nt < 4; nt++) {
                    int col = warp_n + nt * 8 + 2 * lc;
                    *(float2*)&st[row * 132 + col] =
                        make_float2(c[mt][nt][2 * hh + 0], c[mt][nt][2 * hh + 1]);
                }
            }
        __syncthreads();

        float4 scv = *(const float4*)(nsc + lane * 4);
        float invf[4];
#pragma unroll
        for (int j = 0; j < 4; j++) {
            int i = (lane * 4 + j) & 63;
            invf[j] = 1.f / powf(10000.f, (float)i / 64.f);
        }
        const float sgn = (lane < 16) ? -1.f : 1.f;

        for (int rr = 0; rr < 16; rr++) {
            int row = wid * 16 + rr;
            float4 x = *(const float4*)&st[row * 132 + lane * 4];
            float ss = x.x * x.x + x.y * x.y + x.z * x.z + x.w * x.w;
#pragma unroll
            for (int o = 16; o; o >>= 1) ss += __shfl_xor_sync(0xffffffffu, ss, o);
            float inv = rsqrtf(ss * (1.f / 128.f) + 1e-6f);
            float xn[4];
            xn[0] = x.x * inv * scv.x;
            xn[1] = x.y * inv * scv.y;
            xn[2] = x.z * inv * scv.z;
            xn[3] = x.w * inv * scv.w;
            float pr[4];
#pragma unroll
            for (int j = 0; j < 4; j++) pr[j] = __shfl_xor_sync(0xffffffffu, xn[j], 16);
            float pos = (float)(tok0 + row);
            float4 outv;
#pragma unroll
            for (int j = 0; j < 4; j++) {
                float ang = pos * invf[j];
                float cs = cosf(ang), sn2 = sinf(ang);
                ((float*)&outv)[j] = xn[j] * cs + sgn * pr[j] * sn2;
            }
            *(float4*)&C[(size_t)(bm + row) * ldc + bn + lane * 4] = outv;
        }
        return;
    }

#pragma unroll
    for (int mt = 0; mt < 4; mt++) {
#pragma unroll
        for (int hh = 0; hh < 2; hh++) {
            int row = bm + warp_m + mt * 16 + hh * 8 + lr;
            if (row >= M) continue;
#pragma unroll
            for (int nt = 0; nt < 4; nt++) {
                int col = bn + warp_n + nt * 8 + 2 * lc;
                float v0 = c[mt][nt][2 * hh + 0];
                float v1 = c[mt][nt][2 * hh + 1];
                if (BIAS) { v0 += bias[col]; v1 += bias[col + 1]; }
                if (SILU) {
                    v0 = __fdividef(v0, 1.f + __expf(-v0));
                    v1 = __fdividef(v1, 1.f + __expf(-v1));
                }
                if (RESID) {
                    v0 += resid[(size_t)row * ldc + col];
                    v1 += resid[(size_t)row * ldc + col + 1];
                }
                *(float2*)&C[(size_t)row * ldc + col] = make_float2(v0, v1);
            }
        }
    }
}

// persistent fused Q/K/V projection + RMSNorm + RoPE (+ global counter init)
__global__ __launch_bounds__(256, 2)
void k_qkv(const float* __restrict__ x,
           const float* __restrict__ wq, const float* __restrict__ wk,
           const float* __restrict__ wv,
           float* __restrict__ q, float* __restrict__ k, float* __restrict__ v,
           const float* __restrict__ qs, const float* __restrict__ ks)
{
    if (blockIdx.x == 0) {
        const int tid = threadIdx.x;
        if (tid < 16) { g_hc[tid] = 0; g_cnt[tid] = 0; g_fill[tid] = 0; }
        else if (tid < 80) g_upc[tid - 16] = 0;
        else if (tid == 80) g_dnc = 0;
        else if (tid == 81) g_rc = 0;
    }
    for (int t = blockIdx.x; t < 384; t += gridDim.x) {
        const int bx = t % 24;
        const int bm = (t / 24) * 128;
        __syncthreads();
        if (bx < 16)
            gemm_tc<false, false, false, false, true>(
                x, HD, nullptr, wq, NHQ * DH, q, NHQ * DH,
                nullptr, nullptr, TT, HD, bm, bx * 128, qs, bm);
        else if (bx < 20)
            gemm_tc<false, false, false, false, true>(
                x, HD, nullptr, wk, NHKV * DH, k, NHKV * DH,
                nullptr, nullptr, TT, HD, bm, (bx - 16) * 128, ks, bm);
        else
            gemm_tc<false, false, false, false, false>(
                x, HD, nullptr, wv, NHKV * DH, v, NHKV * DH,
                nullptr, nullptr, TT, HD, bm, (bx - 20) * 128);
    }
}

// persistent resid GEMM + fused router (gated) + inline top-2 + routing epilogue
__global__ __launch_bounds__(256, 2)
void k_resid_router(const float* __restrict__ A, const float* __restrict__ B,
                    float* __restrict__ C, const float* __restrict__ resid,
                    const float* __restrict__ rw,
                    float* __restrict__ out2)
{
    const int tid = threadIdx.x;
    const int wid = tid >> 5;
    const int lane = tid & 31;

    for (int t = blockIdx.x; t < 256; t += gridDim.x) {
        __syncthreads();
        gemm_tc<false, false, false, true, false>(
            A, HD, nullptr, B, HD, C, HD,
            nullptr, resid, TT, HD, (t >> 4) * 128, (t & 15) * 128);
        __threadfence();
        __syncthreads();
        if (tid == 0) atomicAdd(&g_hc[t >> 4], 1);
    }

    // router: 8 tokens per block iteration, gated on h m-tile completion
    for (int tb = blockIdx.x * 8; tb < TT; tb += gridDim.x * 8) {
        if (tid == 0) {
            while (atomicAdd(&g_hc[tb >> 7], 0) < 16) { __nanosleep(64); }
            __threadfence();
        }
        __syncthreads();
        const int tok = tb + wid;
        const float* xr = C + (size_t)tok * HD;
        float acc[NE];
#pragma unroll
        for (int e = 0; e < NE; e++) acc[e] = 0.f;
        for (int hh = lane; hh < HD; hh += 32) {
            float xv = xr[hh];
            const float* wr = rw + hh * NE;
#pragma unroll
            for (int e = 0; e < NE; e++) acc[e] += xv * wr[e];
        }
#pragma unroll
        for (int e = 0; e < NE; e++)
#pragma unroll
            for (int o = 16; o; o >>= 1) acc[e] += __shfl_xor_sync(0xffffffffu, acc[e], o);
        if (lane == 0) {
#pragma unroll
            for (int e = 0; e < NE; e++) out2[tok * NE + e] = acc[e];
            int i0 = 0; float v0 = acc[0];
#pragma unroll
            for (int e = 1; e < NE; e++) { if (acc[e] > v0) { v0 = acc[e]; i0 = e; } }
            int i1 = -1; float v1 = -FLT_MAX;
#pragma unroll
            for (int e = 0; e < NE; e++) {
                if (e == i0) continue;
                if (acc[e] > v1) { v1 = acc[e]; i1 = e; }
            }
            g_sel[tok * 2] = i0;
            g_sel[tok * 2 + 1] = i1;
            atomicAdd(&g_cnt[i0], 1);
            atomicAdd(&g_cnt[i1], 1);
        }
        __syncthreads();
        if (tid == 0) { __threadfence(); atomicAdd(&g_rc, 1); }
    }

    // routing epilogue on block 0: offsets + m-tile table + fill
    if (blockIdx.x == 0) {
        if (tid == 0) {
            while (atomicAdd(&g_rc, 0) < TT / 8) { __nanosleep(128); }
            __threadfence();
            int s = 0, nmt = 0;
            for (int e = 0; e < NE; e++) {
                int cnt = g_cnt[e];
                g_off[e] = s;
                for (int bm = 0; bm < cnt; bm += 128) {
                    g_mt_e[nmt] = e;
                    g_mt_bm[nmt] = bm;
                    nmt++;
                }
                s += cnt;
            }
            g_nmt = nmt;
        }
        __syncthreads();
        for (int t = tid; t < TT; t += 256) {
#pragma unroll
            for (int j = 0; j < 2; j++) {
                int e = g_sel[t * 2 + j];
                int pos = atomicAdd(&g_fill[e], 1);
                int slot = g_off[e] + pos;
                g_tok[slot] = t;
                g_slot[t * 2 + j] = slot;
            }
        }
        __threadfence();
        __syncthreads();
        if (tid == 0) atomicExch(&g_nmt, g_nmt | 0x10000);   // publish "table ready"
    }
}

// fused persistent MoE: ups, gated downs, in-kernel final combine.
__global__ __launch_bounds__(256, 2)
void k_moe(const float* __restrict__ h,
           const float* __restrict__ w_up, const float* __restrict__ b_up,
           const float* __restrict__ w_down, const float* __restrict__ b_down,
           float* __restrict__ out)
{
    // wait for routing table publication (set by k_resid_router block 0;
    // k_moe launches after it, but graph capture may overlap tails — cheap guard)
    __shared__ int s_nmt;
    if (threadIdx.x == 0) {
        int v;
        while (((v = atomicAdd(&g_nmt, 0)) & 0x10000) == 0) { __nanosleep(128); }
        __threadfence();
        s_nmt = v & 0xFFFF;
    }
    __syncthreads();
    const int nmt = s_nmt;
    const int ups = nmt * 6;
    const int downs = nmt * 16;
    const int total = ups + downs;
    for (int t = blockIdx.x; t < total; t += gridDim.x) {
        __syncthreads();
        if (t < ups) {
            const int mt = t / 6;
            const int bn = (t % 6) * 128;
            const int e  = g_mt_e[mt];
            const int bm = g_mt_bm[mt];
            gemm_tc<true, true, true, false, false>(
                h, HD, g_tok + g_off[e],
                w_up + (size_t)e * HD * NI, NI,
                g_up + (size_t)g_off[e] * NI, NI,
                b_up + (size_t)e * NI, nullptr,
                g_cnt[e], HD, bm, bn);
            __threadfence();
            __syncthreads();
            if (threadIdx.x == 0) atomicAdd(&g_upc[mt], 1);
        } else {
            const int d  = t - ups;
            const int mt = d / 16;
            const int bn = (d % 16) * 128;
            const int e  = g_mt_e[mt];
            const int bm = g_mt_bm[mt];
            if (threadIdx.x == 0) {
                while (atomicAdd(&g_upc[mt], 0) < 6) { __nanosleep(64); }
                __threadfence();
            }
            __syncthreads();
            gemm_tc<false, true, false, false, false>(
                g_up + (size_t)g_off[e] * NI, NI, nullptr,
                w_down + (size_t)e * NI * HD, HD,
                g_down + (size_t)g_off[e] * HD, HD,
                b_down + (size_t)e * HD, nullptr,
                g_cnt[e], NI, bm, bn);
            __threadfence();
            __syncthreads();
            if (threadIdx.x == 0) atomicAdd(&g_dnc, 1);
        }
    }

    if (threadIdx.x == 0) {
        while (atomicAdd(&g_dnc, 0) < downs) { __nanosleep(128); }
        __threadfence();
    }
    __syncthreads();
    const int stride = gridDim.x * 256;
    for (int i4 = blockIdx.x * 256 + threadIdx.x; i4 < (TT * HD) / 4; i4 += stride) {
        int tt = i4 >> 9;
        int c4 = i4 & 511;
        int s0 = g_slot[tt * 2];
        int s1 = g_slot[tt * 2 + 1];
        float4 hv = *(const float4*)&g_h[(size_t)i4 * 4];
        float4 d0 = *(const float4*)&g_down[((size_t)s0 * HD) + c4 * 4];
        float4 d1 = *(const float4*)&g_down[((size_t)s1 * HD) + c4 * 4];
        float4 o;
        o.x = hv.x + d0.x + d1.x;
        o.y = hv.y + d0.y + d1.y;
        o.z = hv.z + d0.z + d1.z;
        o.w = hv.w + d0.w + d1.w;
        *(float4*)&out[(size_t)i4 * 4] = o;
    }
}

// ---------------- tf32 tensor-core flash attention (persistent, base-2 softmax) ----------------
#define QLD 132
#define KLD 132
#define VLD 136
#define PLD 68

__global__ __launch_bounds__(256)
void k_attn_tc(const float* __restrict__ q, const float* __restrict__ k,
               const float* __restrict__ v, float* __restrict__ o)
{
    extern __shared__ float sm[];
    float* Qs = sm;
    float* Ks = Qs + 128 * QLD;
    float* Vs = Ks + 64 * KLD;
    float* Ps = Vs + 64 * VLD;

    const int tid = threadIdx.x;
    const int wid = tid >> 5;
    const int lane = tid & 31;
    const int lr = lane >> 2;
    const int lc = lane & 3;
    const int wm = wid * 16;
    const float scale2 = 0.12751744f;

    int ldr[8], ldd[8];
#pragma unroll
    for (int i = 0; i < 8; i++) {
        int idx = tid + 256 * i;
        ldr[i] = idx >> 5;
        ldd[i] = (idx & 31) << 2;
    }

#pragma unroll 1
    for (int pass = 0; pass < 2; pass++) {
        const int f = (pass == 0) ? (int)blockIdx.x : 295 - (int)blockIdx.x;
        if (f >= 256) continue;
        const int qt = 15 - (f >> 4);
        const int h  = f & 15;
        const int kh = h >> 2;
        const int q0 = qt * 128;

        __syncthreads();

        for (int idx = tid; idx < 4096; idx += 256) {
            int r = idx >> 5;
            int d4 = (idx & 31) << 2;
            *(float4*)&Qs[r * QLD + d4] =
                *(const float4*)(q + (size_t)(q0 + r) * (NHQ * DH) + h * DH + d4);
        }

        float oacc[16][4];
#pragma unroll
        for (int nt = 0; nt < 16; nt++)
#pragma unroll
            for (int i = 0; i < 4; i++) oacc[nt][i] = 0.f;
        float m0 = -FLT_MAX, m1 = -FLT_MAX, l0 = 0.f, l1 = 0.f;

        const int r0g = q0 + wm + lr;
        const int r1g = r0g + 8;
        const int ntiles = 2 * qt + 2;

        float4 kreg[8], vreg[8];
#pragma unroll
        for (int i = 0; i < 8; i++) {
            kreg[i] = *(const float4*)(k + (size_t)ldr[i] * (NHKV * DH) + kh * DH + ldd[i]);
            vreg[i] = *(const float4*)(v + (size_t)ldr[i] * (NHKV * DH) + kh * DH + ldd[i]);
        }

        for (int tile = 0; tile < ntiles; ++tile) {
            const int k0 = tile * 64;
            __syncthreads();
#pragma unroll
            for (int i = 0; i < 8; i++) {
                *(float4*)&Ks[ldr[i] * KLD + ldd[i]] = kreg[i];
                *(float4*)&Vs[ldr[i] * VLD + ldd[i]] = vreg[i];
            }
            __syncthreads();

            if (tile + 1 < ntiles) {
                const int kn = (tile + 1) * 64;
#pragma unroll
                for (int i = 0; i < 8; i++) {
                    kreg[i] = *(const float4*)(k + (size_t)(kn + ldr[i]) * (NHKV * DH) + kh * DH + ldd[i]);
                    vreg[i] = *(const float4*)(v + (size_t)(kn + ldr[i]) * (NHKV * DH) + kh * DH + ldd[i]);
                }
            }

            float sa[8][4];
#pragma unroll
            for (int nt = 0; nt < 8; nt++)
#pragma unroll
                for (int i = 0; i < 4; i++) sa[nt][i] = 0.f;

#pragma unroll
            for (int dk = 0; dk < 16; ++dk) {
                const int kb = dk * 8;
                uint32_t a[4];
                a[0] = __float_as_uint(Qs[(wm + lr) * QLD + kb + lc]);
                a[1] = __float_as_uint(Qs[(wm + lr + 8) * QLD + kb + lc]);
                a[2] = __float_as_uint(Qs[(wm + lr) * QLD + kb + 4 + lc]);
                a[3] = __float_as_uint(Qs[(wm + lr + 8) * QLD + kb + 4 + lc]);
#pragma unroll
                for (int nt = 0; nt < 8; nt++) {
                    uint32_t b[2];
                    b[0] = __float_as_uint(Ks[(nt * 8 + lr) * KLD + kb + lc]);
                    b[1] = __float_as_uint(Ks[(nt * 8 + lr) * KLD + kb + 4 + lc]);
                    mma_tf32(sa[nt], a, b);
                }
            }

            float mx0 = -FLT_MAX, mx1 = -FLT_MAX;
#pragma unroll
            for (int nt = 0; nt < 8; nt++) {
                int cc = k0 + nt * 8 + 2 * lc;
                sa[nt][0] = (cc     <= r0g) ? sa[nt][0] * scale2 : -FLT_MAX;
                sa[nt][1] = (cc + 1 <= r0g) ? sa[nt][1] * scale2 : -FLT_MAX;
                sa[nt][2] = (cc     <= r1g) ? sa[nt][2] * scale2 : -FLT_MAX;
                sa[nt][3] = (cc + 1 <= r1g) ? sa[nt][3] * scale2 : -FLT_MAX;
                mx0 = fmaxf(mx0, fmaxf(sa[nt][0], sa[nt][1]));
                mx1 = fmaxf(mx1, fmaxf(sa[nt][2], sa[nt][3]));
            }
            mx0 = fmaxf(mx0, __shfl_xor_sync(0xffffffffu, mx0, 1));
            mx0 = fmaxf(mx0, __shfl_xor_sync(0xffffffffu, mx0, 2));
            mx1 = fmaxf(mx1, __shfl_xor_sync(0xffffffffu, mx1, 1));
            mx1 = fmaxf(mx1, __shfl_xor_sync(0xffffffffu, mx1, 2));

            float mn0 = fmaxf(m0, mx0), mn1 = fmaxf(m1, mx1);
            float al0 = fexp2(m0 - mn0), al1 = fexp2(m1 - mn1);

            float ps0 = 0.f, ps1 = 0.f;
#pragma unroll
            for (int nt = 0; nt < 8; nt++) {
                sa[nt][0] = fexp2(sa[nt][0] - mn0);
                sa[nt][1] = fexp2(sa[nt][1] - mn0);
                sa[nt][2] = fexp2(sa[nt][2] - mn1);
                sa[nt][3] = fexp2(sa[nt][3] - mn1);
                ps0 += sa[nt][0] + sa[nt][1];
                ps1 += sa[nt][2] + sa[nt][3];
            }
            ps0 += __shfl_xor_sync(0xffffffffu, ps0, 1);
            ps0 += __shfl_xor_sync(0xffffffffu, ps0, 2);
            ps1 += __shfl_xor_sync(0xffffffffu, ps1, 1);
            ps1 += __shfl_xor_sync(0xffffffffu, ps1, 2);

            l0 = l0 * al0 + ps0;
            l1 = l1 * al1 + ps1;
            m0 = mn0; m1 = mn1;

#pragma unroll
            for (int nt = 0; nt < 16; nt++) {
                oacc[nt][0] *= al0; oacc[nt][1] *= al0;
                oacc[nt][2] *= al1; oacc[nt][3] *= al1;
            }

#pragma unroll
            for (int nt = 0; nt < 8; nt++) {
                int cc = nt * 8 + 2 * lc;
                *(float2*)&Ps[(wm + lr) * PLD + cc]     = make_float2(sa[nt][0], sa[nt][1]);
                *(float2*)&Ps[(wm + lr + 8) * PLD + cc] = make_float2(sa[nt][2], sa[nt][3]);
            }
            __syncwarp();

#pragma unroll
            for (int kc = 0; kc < 8; ++kc) {
                const int kb = kc * 8;
                uint32_t a[4];
                a[0] = __float_as_uint(Ps[(wm + lr) * PLD + kb + lc]);
                a[1] = __float_as_uint(Ps[(wm + lr + 8) * PLD + kb + lc]);
                a[2] = __float_as_uint(Ps[(wm + lr) * PLD + kb + 4 + lc]);
                a[3] = __float_as_uint(Ps[(wm + lr + 8) * PLD + kb + 4 + lc]);
#pragma unroll
                for (int nt = 0; nt < 16; nt++) {
                    uint32_t b[2];
                    b[0] = __float_as_uint(Vs[(kb + lc) * VLD + nt * 8 + lr]);
                    b[1] = __float_as_uint(Vs[(kb + 4 + lc) * VLD + nt * 8 + lr]);
                    mma_tf32(oacc[nt], a, b);
                }
            }
            __syncwarp();
        }

        float inv0 = 1.f / l0, inv1 = 1.f / l1;
#pragma unroll
        for (int nt = 0; nt < 16; nt++) {
            int cc = nt * 8 + 2 * lc;
            size_t o0 = (size_t)r0g * (NHQ * DH) + h * DH + cc;
            size_t o1 = (size_t)r1g * (NHQ * DH) + h * DH + cc;
            *(float2*)&o[o0] = make_float2(oacc[nt][0] * inv0, oacc[nt][1] * inv0);
            *(float2*)&o[o1] = make_float2(oacc[nt][2] * inv1, oacc[nt][3] * inv1);
        }
    }
}

// ---------------- launch ----------------
extern "C" void kernel_launch(void* const* d_in, const int* in_sizes, int n_in,
                              void* d_out, int out_size)
{
    const float* hidden   = (const float*)d_in[0];
    const float* wq       = (const float*)d_in[1];
    const float* wk       = (const float*)d_in[2];
    const float* wv       = (const float*)d_in[3];
    const float* wo       = (const float*)d_in[4];
    const float* q_scale  = (const float*)d_in[5];
    const float* k_scale  = (const float*)d_in[6];
    const float* router_w = (const float*)d_in[7];
    const float* w_up     = (const float*)d_in[8];
    const float* b_up     = (const float*)d_in[9];
    const float* w_down   = (const float*)d_in[10];
    const float* b_down   = (const float*)d_in[11];
    float* out = (float*)d_out;

    float *qb, *kb, *vb, *ab, *hb;
    cudaGetSymbolAddress((void**)&qb, g_q);
    cudaGetSymbolAddress((void**)&kb, g_k);
    cudaGetSymbolAddress((void**)&vb, g_v);
    cudaGetSymbolAddress((void**)&ab, g_attn);
    cudaGetSymbolAddress((void**)&hb, g_h);

    cudaFuncSetAttribute(k_qkv, cudaFuncAttributeMaxDynamicSharedMemorySize, GEMM_SMEM);
    cudaFuncSetAttribute(k_resid_router, cudaFuncAttributeMaxDynamicSharedMemorySize, GEMM_SMEM);
    cudaFuncSetAttribute(k_moe, cudaFuncAttributeMaxDynamicSharedMemorySize, GEMM_SMEM);

    k_qkv<<<296, 256, GEMM_SMEM>>>(hidden, wq, wk, wv, qb, kb, vb, q_scale, k_scale);

    const int attn_smem = (128 * QLD + 64 * KLD + 64 * VLD + 128 * PLD) * 4;
    cudaFuncSetAttribute(k_attn_tc, cudaFuncAttributeMaxDynamicSharedMemorySize, attn_smem);
    k_attn_tc<<<148, 256, attn_smem>>>(qb, kb, vb, ab);

    // fused O-proj + residual + router + top-2 + routing epilogue
    k_resid_router<<<296, 256, GEMM_SMEM>>>(ab, wo, hb, hidden, router_w,
                                            out + (size_t)TT * HD);

    // fused persistent MoE (waits on routing-table publication)
    k_moe<<<296, 256, GEMM_SMEM>>>(hb, w_up, b_up, w_down, b_down, out);
}

// round 17
// speedup vs baseline: 1.0279x; 1.0279x over previous
#include <cuda_runtime.h>
#include <math.h>
#include <float.h>
#include <stdint.h>

// ---------------- problem constants ----------------
#define TT   2048
#define HD   2048
#define NHQ  16
#define NHKV 4
#define DH   128
#define NE   16
#define NI   768

// ---------------- device scratch ----------------
__device__ float g_q[TT * NHQ * DH];
__device__ float g_k[TT * NHKV * DH];
__device__ float g_v[TT * NHKV * DH];
__device__ float g_attn[TT * NHQ * DH];
__device__ float g_h[TT * HD];
__device__ int   g_sel[TT * 2];
__device__ int   g_cnt[NE];
__device__ int   g_off[NE];
__device__ int   g_tok[TT * 2];
__device__ int   g_slot[TT * 2];
__device__ float g_up[TT * 2 * NI];
__device__ float g_down[TT * 2 * HD];
// flat m-tile table + completion counters
__device__ int   g_mt_e[64];
__device__ int   g_mt_bm[64];
__device__ int   g_nmt;
__device__ int   g_upc[64];
__device__ int   g_dnc;
__device__ int   g_hc[16];

// ---------------- helpers ----------------
__device__ __forceinline__ float fexp2(float x) {
    float y;
    asm("ex2.approx.ftz.f32 %0, %1;" : "=f"(y) : "f"(x));
    return y;
}

__device__ __forceinline__ void mma_tf32(float c[4], const uint32_t a[4], const uint32_t b[2]) {
    asm volatile(
        "mma.sync.aligned.m16n8k8.row.col.f32.tf32.tf32.f32 "
        "{%0,%1,%2,%3}, {%4,%5,%6,%7}, {%8,%9}, {%0,%1,%2,%3};"
        : "+f"(c[0]), "+f"(c[1]), "+f"(c[2]), "+f"(c[3])
        : "r"(a[0]), "r"(a[1]), "r"(a[2]), "r"(a[3]), "r"(b[0]), "r"(b[1]));
}

__device__ __forceinline__ void ldsm4(uint32_t a[4], uint32_t addr) {
    asm volatile("ldmatrix.sync.aligned.m8n8.x4.shared.b16 {%0,%1,%2,%3}, [%4];"
                 : "=r"(a[0]), "=r"(a[1]), "=r"(a[2]), "=r"(a[3]) : "r"(addr));
}

__device__ __forceinline__ void cpa16(uint32_t dst, const void* src, bool pred) {
    int sz = pred ? 16 : 0;
    asm volatile("cp.async.cg.shared.global [%0], [%1], 16, %2;\n"
                 :: "r"(dst), "l"(src), "r"(sz));
}
__device__ __forceinline__ void cp_commit() {
    asm volatile("cp.async.commit_group;\n" ::: "memory");
}
__device__ __forceinline__ void cp_wait0() {
    asm volatile("cp.async.wait_group 0;\n" ::: "memory");
}
__device__ __forceinline__ void cp_wait1() {
    asm volatile("cp.async.wait_group 1;\n" ::: "memory");
}

// ---------------- mma.sync tf32 GEMM core ----------------
#define AST 36
#define BST 136
#define ASZ (128 * AST)
#define BSZ (32 * BST)
#define NSTG 3
#define GEMM_SMEM ((NSTG * ASZ + NSTG * BSZ) * 4)

template<bool GATHER, bool BIAS, bool SILU, bool RESID, bool QKROPE>
__device__ __forceinline__ void gemm_tc(
    const float* __restrict__ A, int lda, const int* __restrict__ gidx,
    const float* __restrict__ B, int ldb,
    float* __restrict__ C, int ldc,
    const float* __restrict__ bias,
    const float* __restrict__ resid,
    int M, int K, int bm, int bn,
    const float* __restrict__ nsc = nullptr, int tok0 = 0)
{
    extern __shared__ float smem[];
    float* As = smem;
    float* Bs = smem + NSTG * ASZ;

    const int tid  = threadIdx.x;
    const int wid  = tid >> 5;
    const int lane = tid & 31;
    const int warp_m = (wid >> 2) * 64;
    const int warp_n = (wid & 3) * 32;
    const int lr = lane >> 2;
    const int lc = lane & 3;
    const int lrow = lane & 7;
    const int sel  = lane >> 3;

    float c[4][4][4];
#pragma unroll
    for (int mt = 0; mt < 4; mt++)
#pragma unroll
        for (int nt = 0; nt < 4; nt++)
#pragma unroll
            for (int i = 0; i < 4; i++) c[mt][nt][i] = 0.f;

    const int am  = tid >> 3;
    const int ak4 = (tid & 7) * 4;
    const int bk  = tid >> 5;
    const int bn4 = (tid & 31) * 4;

    const float* asrc[4];
    bool aok[4];
#pragma unroll
    for (int i = 0; i < 4; i++) {
        int grow = bm + am + 32 * i;
        aok[i] = (grow < M);
        const float* p = A;
        if (aok[i]) p = A + (size_t)(GATHER ? gidx[grow] : grow) * lda;
        asrc[i] = p + ak4;
    }
    const float* bsrc[4];
#pragma unroll
    for (int i = 0; i < 4; i++)
        bsrc[i] = B + (size_t)(bk + 8 * i) * ldb + bn + bn4;

    uint32_t sa = (uint32_t)__cvta_generic_to_shared(As);
    uint32_t sb = (uint32_t)__cvta_generic_to_shared(Bs);
    uint32_t adst[4], bdst[4];
#pragma unroll
    for (int i = 0; i < 4; i++) {
        adst[i] = sa + ((am + 32 * i) * AST + ak4) * 4;
        bdst[i] = sb + ((bk + 8 * i) * BST + bn4) * 4;
    }

    const uint32_t a_lane4 = (((sel & 1) * 8 + lrow) * AST + (sel >> 1) * 4) * 4;
    const uint32_t a_warp = sa + warp_m * AST * 4 + a_lane4;

    const int nch = K >> 5;

#pragma unroll
    for (int i = 0; i < 4; i++) cpa16(adst[i], asrc[i], aok[i]);
#pragma unroll
    for (int i = 0; i < 4; i++) cpa16(bdst[i], bsrc[i], true);
    cp_commit();
    if (nch > 1) {
#pragma unroll
        for (int i = 0; i < 4; i++) cpa16(adst[i] + ASZ * 4, asrc[i] + 32, aok[i]);
#pragma unroll
        for (int i = 0; i < 4; i++) cpa16(bdst[i] + BSZ * 4, bsrc[i] + (size_t)32 * ldb, true);
        cp_commit();
    }

    int sc = 0;
    int sn = (nch > 1) ? 2 : 1;
    for (int ch = 0; ch < nch; ch++) {
        if (ch + 1 < nch) cp_wait1(); else cp_wait0();
        __syncthreads();

        if (ch + 2 < nch) {
            const int koff = (ch + 2) * 32;
            const uint32_t ao = sn * (ASZ * 4);
            const uint32_t bo = sn * (BSZ * 4);
#pragma unroll
            for (int i = 0; i < 4; i++) cpa16(adst[i] + ao, asrc[i] + koff, aok[i]);
#pragma unroll
            for (int i = 0; i < 4; i++) cpa16(bdst[i] + bo, bsrc[i] + (size_t)koff * ldb, true);
            cp_commit();
            sn = (sn + 1 == NSTG) ? 0 : sn + 1;
        }

        const float* Bc = Bs + sc * BSZ;
        const uint32_t a_base = a_warp + sc * (ASZ * 4);
        sc = (sc + 1 == NSTG) ? 0 : sc + 1;

#pragma unroll
        for (int ks = 0; ks < 4; ks++) {
            const int kb = ks * 8;
            uint32_t a[4][4];
#pragma unroll
            for (int mt = 0; mt < 4; mt++)
                ldsm4(a[mt], a_base + mt * (16 * AST * 4) + ks * 32);

            uint32_t b[4][2];
#pragma unroll
            for (int nt = 0; nt < 4; nt++) {
                int col = warp_n + nt * 8 + lr;
                b[nt][0] = __float_as_uint(Bc[(kb + lc) * BST + col]);
                b[nt][1] = __float_as_uint(Bc[(kb + 4 + lc) * BST + col]);
            }
#pragma unroll
            for (int mt = 0; mt < 4; mt++)
#pragma unroll
                for (int nt = 0; nt < 4; nt++)
                    mma_tf32(c[mt][nt], a[mt], b[nt]);
        }
    }

    if (QKROPE) {
        __syncthreads();
        float* st = smem;
#pragma unroll
        for (int mt = 0; mt < 4; mt++)
#pragma unroll
            for (int hh = 0; hh < 2; hh++) {
                int row = warp_m + mt * 16 + hh * 8 + lr;
#pragma unroll
                for (int nt = 0; nt < 4; nt++) {
                    int col = warp_n + nt * 8 + 2 * lc;
                    *(float2*)&st[row * 132 + col] =
                        make_float2(c[mt][nt][2 * hh + 0], c[mt][nt][2 * hh + 1]);
                }
            }
        __syncthreads();

        float4 scv = *(const float4*)(nsc + lane * 4);
        float invf[4];
#pragma unroll
        for (int j = 0; j < 4; j++) {
            int i = (lane * 4 + j) & 63;
            invf[j] = 1.f / powf(10000.f, (float)i / 64.f);
        }
        const float sgn = (lane < 16) ? -1.f : 1.f;

        for (int rr = 0; rr < 16; rr++) {
            int row = wid * 16 + rr;
            float4 x = *(const float4*)&st[row * 132 + lane * 4];
            float ss = x.x * x.x + x.y * x.y + x.z * x.z + x.w * x.w;
#pragma unroll
            for (int o = 16; o; o >>= 1) ss += __shfl_xor_sync(0xffffffffu, ss, o);
            float inv = rsqrtf(ss * (1.f / 128.f) + 1e-6f);
            float xn[4];
            xn[0] = x.x * inv * scv.x;
            xn[1] = x.y * inv * scv.y;
            xn[2] = x.z * inv * scv.z;
            xn[3] = x.w * inv * scv.w;
            float pr[4];
#pragma unroll
            for (int j = 0; j < 4; j++) pr[j] = __shfl_xor_sync(0xffffffffu, xn[j], 16);
            float pos = (float)(tok0 + row);
            float4 outv;
#pragma unroll
            for (int j = 0; j < 4; j++) {
                float ang = pos * invf[j];
                float cs = cosf(ang), sn2 = sinf(ang);
                ((float*)&outv)[j] = xn[j] * cs + sgn * pr[j] * sn2;
            }
            *(float4*)&C[(size_t)(bm + row) * ldc + bn + lane * 4] = outv;
        }
        return;
    }

#pragma unroll
    for (int mt = 0; mt < 4; mt++) {
#pragma unroll
        for (int hh = 0; hh < 2; hh++) {
            int row = bm + warp_m + mt * 16 + hh * 8 + lr;
            if (row >= M) continue;
#pragma unroll
            for (int nt = 0; nt < 4; nt++) {
                int col = bn + warp_n + nt * 8 + 2 * lc;
                float v0 = c[mt][nt][2 * hh + 0];
                float v1 = c[mt][nt][2 * hh + 1];
                if (BIAS) { v0 += bias[col]; v1 += bias[col + 1]; }
                if (SILU) {
                    v0 = __fdividef(v0, 1.f + __expf(-v0));
                    v1 = __fdividef(v1, 1.f + __expf(-v1));
                }
                if (RESID) {
                    v0 += resid[(size_t)row * ldc + col];
                    v1 += resid[(size_t)row * ldc + col + 1];
                }
                *(float2*)&C[(size_t)row * ldc + col] = make_float2(v0, v1);
            }
        }
    }
}

// persistent fused Q/K/V projection + RMSNorm + RoPE (+ global counter init)
__global__ __launch_bounds__(256, 2)
void k_qkv(const float* __restrict__ x,
           const float* __restrict__ wq, const float* __restrict__ wk,
           const float* __restrict__ wv,
           float* __restrict__ q, float* __restrict__ k, float* __restrict__ v,
           const float* __restrict__ qs, const float* __restrict__ ks)
{
    if (blockIdx.x == 0) {
        const int tid = threadIdx.x;
        if (tid < 16) { g_hc[tid] = 0; g_cnt[tid] = 0; }
        else if (tid < 80) g_upc[tid - 16] = 0;
        else if (tid == 80) g_dnc = 0;
    }
    for (int t = blockIdx.x; t < 384; t += gridDim.x) {
        const int bx = t % 24;
        const int bm = (t / 24) * 128;
        __syncthreads();
        if (bx < 16)
            gemm_tc<false, false, false, false, true>(
                x, HD, nullptr, wq, NHQ * DH, q, NHQ * DH,
                nullptr, nullptr, TT, HD, bm, bx * 128, qs, bm);
        else if (bx < 20)
            gemm_tc<false, false, false, false, true>(
                x, HD, nullptr, wk, NHKV * DH, k, NHKV * DH,
                nullptr, nullptr, TT, HD, bm, (bx - 16) * 128, ks, bm);
        else
            gemm_tc<false, false, false, false, false>(
                x, HD, nullptr, wv, NHKV * DH, v, NHKV * DH,
                nullptr, nullptr, TT, HD, bm, (bx - 20) * 128);
    }
}

// persistent resid GEMM + fused router (gated) + inline top-2
__global__ __launch_bounds__(256, 2)
void k_resid_router(const float* __restrict__ A, const float* __restrict__ B,
                    float* __restrict__ C, const float* __restrict__ resid,
                    const float* __restrict__ rw,
                    float* __restrict__ out2)
{
    const int tid = threadIdx.x;
    const int wid = tid >> 5;
    const int lane = tid & 31;

    for (int t = blockIdx.x; t < 256; t += gridDim.x) {
        __syncthreads();
        gemm_tc<false, false, false, true, false>(
            A, HD, nullptr, B, HD, C, HD,
            nullptr, resid, TT, HD, (t >> 4) * 128, (t & 15) * 128);
        __threadfence();
        __syncthreads();
        if (tid == 0) atomicAdd(&g_hc[t >> 4], 1);
    }

    for (int tb = blockIdx.x * 8; tb < TT; tb += gridDim.x * 8) {
        if (tid == 0) {
            while (atomicAdd(&g_hc[tb >> 7], 0) < 16) { __nanosleep(64); }
            __threadfence();
        }
        __syncthreads();
        const int tok = tb + wid;
        const float* xr = C + (size_t)tok * HD;
        float acc[NE];
#pragma unroll
        for (int e = 0; e < NE; e++) acc[e] = 0.f;
        for (int hh = lane; hh < HD; hh += 32) {
            float xv = xr[hh];
            const float* wr = rw + hh * NE;
#pragma unroll
            for (int e = 0; e < NE; e++) acc[e] += xv * wr[e];
        }
#pragma unroll
        for (int e = 0; e < NE; e++)
#pragma unroll
            for (int o = 16; o; o >>= 1) acc[e] += __shfl_xor_sync(0xffffffffu, acc[e], o);
        if (lane == 0) {
#pragma unroll
            for (int e = 0; e < NE; e++) out2[tok * NE + e] = acc[e];
            // inline top-2 from registers
            int i0 = 0; float v0 = acc[0];
#pragma unroll
            for (int e = 1; e < NE; e++) { if (acc[e] > v0) { v0 = acc[e]; i0 = e; } }
            int i1 = -1; float v1 = -FLT_MAX;
#pragma unroll
            for (int e = 0; e < NE; e++) {
                if (e == i0) continue;
                if (acc[e] > v1) { v1 = acc[e]; i1 = e; }
            }
            g_sel[tok * 2] = i0;
            g_sel[tok * 2 + 1] = i1;
            atomicAdd(&g_cnt[i0], 1);
            atomicAdd(&g_cnt[i1], 1);
        }
    }
}

// fused persistent MoE: ups, gated downs, in-kernel final combine.
__global__ __launch_bounds__(256, 2)
void k_moe(const float* __restrict__ h,
           const float* __restrict__ w_up, const float* __restrict__ b_up,
           const float* __restrict__ w_down, const float* __restrict__ b_down,
           float* __restrict__ out)
{
    const int nmt = g_nmt;
    const int ups = nmt * 6;
    const int downs = nmt * 16;
    const int total = ups + downs;
    for (int t = blockIdx.x; t < total; t += gridDim.x) {
        __syncthreads();
        if (t < ups) {
            const int mt = t / 6;
            const int bn = (t % 6) * 128;
            const int e  = g_mt_e[mt];
            const int bm = g_mt_bm[mt];
            gemm_tc<true, true, true, false, false>(
                h, HD, g_tok + g_off[e],
                w_up + (size_t)e * HD * NI, NI,
                g_up + (size_t)g_off[e] * NI, NI,
                b_up + (size_t)e * NI, nullptr,
                g_cnt[e], HD, bm, bn);
            __threadfence();
            __syncthreads();
            if (threadIdx.x == 0) atomicAdd(&g_upc[mt], 1);
        } else {
            const int d  = t - ups;
            const int mt = d / 16;
            const int bn = (d % 16) * 128;
            const int e  = g_mt_e[mt];
            const int bm = g_mt_bm[mt];
            if (threadIdx.x == 0) {
                while (atomicAdd(&g_upc[mt], 0) < 6) { __nanosleep(64); }
                __threadfence();
            }
            __syncthreads();
            gemm_tc<false, true, false, false, false>(
                g_up + (size_t)g_off[e] * NI, NI, nullptr,
                w_down + (size_t)e * NI * HD, HD,
                g_down + (size_t)g_off[e] * HD, HD,
                b_down + (size_t)e * HD, nullptr,
                g_cnt[e], NI, bm, bn);
            __threadfence();
            __syncthreads();
            if (threadIdx.x == 0) atomicAdd(&g_dnc, 1);
        }
    }

    if (threadIdx.x == 0) {
        while (atomicAdd(&g_dnc, 0) < downs) { __nanosleep(128); }
        __threadfence();
    }
    __syncthreads();
    const int stride = gridDim.x * 256;
    for (int i4 = blockIdx.x * 256 + threadIdx.x; i4 < (TT * HD) / 4; i4 += stride) {
        int tt = i4 >> 9;
        int c4 = i4 & 511;
        int s0 = g_slot[tt * 2];
        int s1 = g_slot[tt * 2 + 1];
        float4 hv = *(const float4*)&g_h[(size_t)i4 * 4];
        float4 d0 = *(const float4*)&g_down[((size_t)s0 * HD) + c4 * 4];
        float4 d1 = *(const float4*)&g_down[((size_t)s1 * HD) + c4 * 4];
        float4 o;
        o.x = hv.x + d0.x + d1.x;
        o.y = hv.y + d0.y + d1.y;
        o.z = hv.z + d0.z + d1.z;
        o.w = hv.w + d0.w + d1.w;
        *(float4*)&out[(size_t)i4 * 4] = o;
    }
}

// ---------------- tf32 tensor-core flash attention (persistent, base-2 softmax) ----------------
#define QLD 132
#define KLD 132
#define VLD 136
#define PLD 68

__global__ __launch_bounds__(256)
void k_attn_tc(const float* __restrict__ q, const float* __restrict__ k,
               const float* __restrict__ v, float* __restrict__ o)
{
    extern __shared__ float sm[];
    float* Qs = sm;
    float* Ks = Qs + 128 * QLD;
    float* Vs = Ks + 64 * KLD;
    float* Ps = Vs + 64 * VLD;

    const int tid = threadIdx.x;
    const int wid = tid >> 5;
    const int lane = tid & 31;
    const int lr = lane >> 2;
    const int lc = lane & 3;
    const int wm = wid * 16;
    const float scale2 = 0.12751744f;

    int ldr[8], ldd[8];
#pragma unroll
    for (int i = 0; i < 8; i++) {
        int idx = tid + 256 * i;
        ldr[i] = idx >> 5;
        ldd[i] = (idx & 31) << 2;
    }

#pragma unroll 1
    for (int pass = 0; pass < 2; pass++) {
        const int f = (pass == 0) ? (int)blockIdx.x : 295 - (int)blockIdx.x;
        if (f >= 256) continue;
        const int qt = 15 - (f >> 4);
        const int h  = f & 15;
        const int kh = h >> 2;
        const int q0 = qt * 128;

        __syncthreads();

        for (int idx = tid; idx < 4096; idx += 256) {
            int r = idx >> 5;
            int d4 = (idx & 31) << 2;
            *(float4*)&Qs[r * QLD + d4] =
                *(const float4*)(q + (size_t)(q0 + r) * (NHQ * DH) + h * DH + d4);
        }

        float oacc[16][4];
#pragma unroll
        for (int nt = 0; nt < 16; nt++)
#pragma unroll
            for (int i = 0; i < 4; i++) oacc[nt][i] = 0.f;
        float m0 = -FLT_MAX, m1 = -FLT_MAX, l0 = 0.f, l1 = 0.f;

        const int r0g = q0 + wm + lr;
        const int r1g = r0g + 8;
        const int ntiles = 2 * qt + 2;

        float4 kreg[8], vreg[8];
#pragma unroll
        for (int i = 0; i < 8; i++) {
            kreg[i] = *(const float4*)(k + (size_t)ldr[i] * (NHKV * DH) + kh * DH + ldd[i]);
            vreg[i] = *(const float4*)(v + (size_t)ldr[i] * (NHKV * DH) + kh * DH + ldd[i]);
        }

        for (int tile = 0; tile < ntiles; ++tile) {
            const int k0 = tile * 64;
            __syncthreads();
#pragma unroll
            for (int i = 0; i < 8; i++) {
                *(float4*)&Ks[ldr[i] * KLD + ldd[i]] = kreg[i];
                *(float4*)&Vs[ldr[i] * VLD + ldd[i]] = vreg[i];
            }
            __syncthreads();

            if (tile + 1 < ntiles) {
                const int kn = (tile + 1) * 64;
#pragma unroll
                for (int i = 0; i < 8; i++) {
                    kreg[i] = *(const float4*)(k + (size_t)(kn + ldr[i]) * (NHKV * DH) + kh * DH + ldd[i]);
                    vreg[i] = *(const float4*)(v + (size_t)(kn + ldr[i]) * (NHKV * DH) + kh * DH + ldd[i]);
                }
            }

            float sa[8][4];
#pragma unroll
            for (int nt = 0; nt < 8; nt++)
#pragma unroll
                for (int i = 0; i < 4; i++) sa[nt][i] = 0.f;

#pragma unroll
            for (int dk = 0; dk < 16; ++dk) {
                const int kb = dk * 8;
                uint32_t a[4];
                a[0] = __float_as_uint(Qs[(wm + lr) * QLD + kb + lc]);
                a[1] = __float_as_uint(Qs[(wm + lr + 8) * QLD + kb + lc]);
                a[2] = __float_as_uint(Qs[(wm + lr) * QLD + kb + 4 + lc]);
                a[3] = __float_as_uint(Qs[(wm + lr + 8) * QLD + kb + 4 + lc]);
#pragma unroll
                for (int nt = 0; nt < 8; nt++) {
                    uint32_t b[2];
                    b[0] = __float_as_uint(Ks[(nt * 8 + lr) * KLD + kb + lc]);
                    b[1] = __float_as_uint(Ks[(nt * 8 + lr) * KLD + kb + 4 + lc]);
                    mma_tf32(sa[nt], a, b);
                }
            }

            float mx0 = -FLT_MAX, mx1 = -FLT_MAX;
#pragma unroll
            for (int nt = 0; nt < 8; nt++) {
                int cc = k0 + nt * 8 + 2 * lc;
                sa[nt][0] = (cc     <= r0g) ? sa[nt][0] * scale2 : -FLT_MAX;
                sa[nt][1] = (cc + 1 <= r0g) ? sa[nt][1] * scale2 : -FLT_MAX;
                sa[nt][2] = (cc     <= r1g) ? sa[nt][2] * scale2 : -FLT_MAX;
                sa[nt][3] = (cc + 1 <= r1g) ? sa[nt][3] * scale2 : -FLT_MAX;
                mx0 = fmaxf(mx0, fmaxf(sa[nt][0], sa[nt][1]));
                mx1 = fmaxf(mx1, fmaxf(sa[nt][2], sa[nt][3]));
            }
            mx0 = fmaxf(mx0, __shfl_xor_sync(0xffffffffu, mx0, 1));
            mx0 = fmaxf(mx0, __shfl_xor_sync(0xffffffffu, mx0, 2));
            mx1 = fmaxf(mx1, __shfl_xor_sync(0xffffffffu, mx1, 1));
            mx1 = fmaxf(mx1, __shfl_xor_sync(0xffffffffu, mx1, 2));

            float mn0 = fmaxf(m0, mx0), mn1 = fmaxf(m1, mx1);
            float al0 = fexp2(m0 - mn0), al1 = fexp2(m1 - mn1);

            float ps0 = 0.f, ps1 = 0.f;
#pragma unroll
            for (int nt = 0; nt < 8; nt++) {
                sa[nt][0] = fexp2(sa[nt][0] - mn0);
                sa[nt][1] = fexp2(sa[nt][1] - mn0);
                sa[nt][2] = fexp2(sa[nt][2] - mn1);
                sa[nt][3] = fexp2(sa[nt][3] - mn1);
                ps0 += sa[nt][0] + sa[nt][1];
                ps1 += sa[nt][2] + sa[nt][3];
            }
            ps0 += __shfl_xor_sync(0xffffffffu, ps0, 1);
            ps0 += __shfl_xor_sync(0xffffffffu, ps0, 2);
            ps1 += __shfl_xor_sync(0xffffffffu, ps1, 1);
            ps1 += __shfl_xor_sync(0xffffffffu, ps1, 2);

            l0 = l0 * al0 + ps0;
            l1 = l1 * al1 + ps1;
            m0 = mn0; m1 = mn1;

#pragma unroll
            for (int nt = 0; nt < 16; nt++) {
                oacc[nt][0] *= al0; oacc[nt][1] *= al0;
                oacc[nt][2] *= al1; oacc[nt][3] *= al1;
            }

#pragma unroll
            for (int nt = 0; nt < 8; nt++) {
                int cc = nt * 8 + 2 * lc;
                *(float2*)&Ps[(wm + lr) * PLD + cc]     = make_float2(sa[nt][0], sa[nt][1]);
                *(float2*)&Ps[(wm + lr + 8) * PLD + cc] = make_float2(sa[nt][2], sa[nt][3]);
            }
            __syncwarp();

#pragma unroll
            for (int kc = 0; kc < 8; ++kc) {
                const int kb = kc * 8;
                uint32_t a[4];
                a[0] = __float_as_uint(Ps[(wm + lr) * PLD + kb + lc]);
                a[1] = __float_as_uint(Ps[(wm + lr + 8) * PLD + kb + lc]);
                a[2] = __float_as_uint(Ps[(wm + lr) * PLD + kb + 4 + lc]);
                a[3] = __float_as_uint(Ps[(wm + lr + 8) * PLD + kb + 4 + lc]);
#pragma unroll
                for (int nt = 0; nt < 16; nt++) {
                    uint32_t b[2];
                    b[0] = __float_as_uint(Vs[(kb + lc) * VLD + nt * 8 + lr]);
                    b[1] = __float_as_uint(Vs[(kb + 4 + lc) * VLD + nt * 8 + lr]);
                    mma_tf32(oacc[nt], a, b);
                }
            }
            __syncwarp();
        }

        float inv0 = 1.f / l0, inv1 = 1.f / l1;
#pragma unroll
        for (int nt = 0; nt < 16; nt++) {
            int cc = nt * 8 + 2 * lc;
            size_t o0 = (size_t)r0g * (NHQ * DH) + h * DH + cc;
            size_t o1 = (size_t)r1g * (NHQ * DH) + h * DH + cc;
            *(float2*)&o[o0] = make_float2(oacc[nt][0] * inv0, oacc[nt][1] * inv0);
            *(float2*)&o[o1] = make_float2(oacc[nt][2] * inv1, oacc[nt][3] * inv1);
        }
    }
}

// ---------------- routing epilogue: offsets + m-tile table + fill ----------------
__global__ __launch_bounds__(1024)
void k_route2()
{
    __shared__ int soff[NE], sfill[NE];
    const int tid = threadIdx.x;
    if (tid == 0) {
        int s = 0, nmt = 0;
        for (int e = 0; e < NE; e++) {
            int cnt = g_cnt[e];
            soff[e] = s;
            g_off[e] = s;
            for (int bm = 0; bm < cnt; bm += 128) {
                g_mt_e[nmt] = e;
                g_mt_bm[nmt] = bm;
                nmt++;
            }
            s += cnt;
            sfill[e] = 0;
        }
        g_nmt = nmt;
    }
    __syncthreads();

    for (int t = tid; t < TT; t += 1024) {
        int e0 = g_sel[t * 2];
        int e1 = g_sel[t * 2 + 1];
        int p0 = atomicAdd(&sfill[e0], 1);
        int s0 = soff[e0] + p0;
        g_tok[s0] = t;
        g_slot[t * 2] = s0;
        int p1 = atomicAdd(&sfill[e1], 1);
        int s1 = soff[e1] + p1;
        g_tok[s1] = t;
        g_slot[t * 2 + 1] = s1;
    }
}

// ---------------- launch ----------------
extern "C" void kernel_launch(void* const* d_in, const int* in_sizes, int n_in,
                              void* d_out, int out_size)
{
    const float* hidden   = (const float*)d_in[0];
    const float* wq       = (const float*)d_in[1];
    const float* wk       = (const float*)d_in[2];
    const float* wv       = (const float*)d_in[3];
    const float* wo       = (const float*)d_in[4];
    const float* q_scale  = (const float*)d_in[5];
    const float* k_scale  = (const float*)d_in[6];
    const float* router_w = (const float*)d_in[7];
    const float* w_up     = (const float*)d_in[8];
    const float* b_up     = (const float*)d_in[9];
    const float* w_down   = (const float*)d_in[10];
    const float* b_down   = (const float*)d_in[11];
    float* out = (float*)d_out;

    float *qb, *kb, *vb, *ab, *hb;
    cudaGetSymbolAddress((void**)&qb, g_q);
    cudaGetSymbolAddress((void**)&kb, g_k);
    cudaGetSymbolAddress((void**)&vb, g_v);
    cudaGetSymbolAddress((void**)&ab, g_attn);
    cudaGetSymbolAddress((void**)&hb, g_h);

    cudaFuncSetAttribute(k_qkv, cudaFuncAttributeMaxDynamicSharedMemorySize, GEMM_SMEM);
    cudaFuncSetAttribute(k_resid_router, cudaFuncAttributeMaxDynamicSharedMemorySize, GEMM_SMEM);
    cudaFuncSetAttribute(k_moe, cudaFuncAttributeMaxDynamicSharedMemorySize, GEMM_SMEM);

    k_qkv<<<296, 256, GEMM_SMEM>>>(hidden, wq, wk, wv, qb, kb, vb, q_scale, k_scale);

    const int attn_smem = (128 * QLD + 64 * KLD + 64 * VLD + 128 * PLD) * 4;
    cudaFuncSetAttribute(k_attn_tc, cudaFuncAttributeMaxDynamicSharedMemorySize, attn_smem);
    k_attn_tc<<<148, 256, attn_smem>>>(qb, kb, vb, ab);

    // fused O-proj + residual + router + top-2
    k_resid_router<<<296, 256, GEMM_SMEM>>>(ab, wo, hb, hidden, router_w,
                                            out + (size_t)TT * HD);

    k_route2<<<1, 1024>>>();

    k_moe<<<296, 256, GEMM_SMEM>>>(hb, w_up, b_up, w_down, b_down, out);
}